// round 13
// baseline (speedup 1.0000x reference)
#include <cuda_runtime.h>
#include <math.h>

#define B_DIM 64
#define K_DIM 128
#define H_DIM 64
#define W_DIM 64
#define PLANE (H_DIM * W_DIM)          // 4096 floats
#define N_PLANES (B_DIM * K_DIM)       // 8192
#define N_BOXES 256
#define N_WORK (N_PLANES + N_BOXES)    // 8448 working blocks
#define N_BLOCKS (N_WORK + 1)          // +1 waiter/finalizer block
#define ALPHA 1.0f
#define BETA 0.5f

// Zero-initialized device globals; waiter resets them each run.
// 0 is below every real value's monotonic encoding -> valid "empty" max.
__device__ unsigned int g_plane_max[N_PLANES];
__device__ float g_box_in[N_BOXES];
__device__ float g_box_out[N_BOXES];
__device__ unsigned int g_done_count;

__device__ __forceinline__ float softplus_f(float x) {
    float ax = fabsf(x);
    return log1pf(expf(-ax)) + fmaxf(x, 0.0f);
}

// Monotonic float <-> uint encoding: float ordering == unsigned ordering.
__device__ __forceinline__ unsigned int enc_f(float f) {
    unsigned int u = __float_as_uint(f);
    return u ^ ((unsigned int)(((int)u) >> 31) | 0x80000000u);
}
__device__ __forceinline__ float dec_f(unsigned int e) {
    unsigned int u = (e & 0x80000000u) ? (e ^ 0x80000000u) : ~e;
    return __uint_as_float(u);
}

// Fire-and-forget reductions (REDG: no return, no round-trip stall).
__device__ __forceinline__ void red_max_u32(unsigned int* addr, unsigned int v) {
    asm volatile("red.global.max.u32 [%0], %1;" :: "l"(addr), "r"(v) : "memory");
}
__device__ __forceinline__ void red_add_f32(float* addr, float v) {
    asm volatile("red.global.add.f32 [%0], %1;" :: "l"(addr), "f"(v) : "memory");
}
__device__ __forceinline__ void red_add_release_gpu(unsigned int* addr, unsigned int v) {
    asm volatile("red.release.gpu.global.add.u32 [%0], %1;"
                 :: "l"(addr), "r"(v) : "memory");
}
__device__ __forceinline__ unsigned int ld_acquire_gpu(const unsigned int* addr) {
    unsigned int v;
    asm volatile("ld.acquire.gpu.global.u32 %0, [%1];" : "=r"(v) : "l"(addr));
    return v;
}

__global__ __launch_bounds__(256) void fused_loss_kernel(
    const float* __restrict__ cams,
    const float* __restrict__ concepts_gt,
    const int* __restrict__ box_b,
    const int* __restrict__ box_c,
    const int* __restrict__ y0v,
    const int* __restrict__ y1v,
    const int* __restrict__ x0v,
    const int* __restrict__ x1v,
    float* __restrict__ out)
{
    int t = threadIdx.x;
    int lid = t & 31;

    if (blockIdx.x == N_WORK) {
        // ================= waiter/finalizer block =================
        __shared__ float sCls[8], sLoc[8];
        if (t == 0) {
            while (ld_acquire_gpu(&g_done_count) != N_WORK)
                __nanosleep(128);
        }
        __syncthreads();

        // cls: 32 planes per thread
        float cls = 0.0f;
#pragma unroll 4
        for (int i = 0; i < 32; i++) {
            int plane = t * 32 + i;
            float bm = dec_f(g_plane_max[plane]);
            g_plane_max[plane] = 0u;                   // reset for replay
            float y = concepts_gt[plane];
            cls += y * softplus_f(-bm) + (1.0f - y) * softplus_f(bm);
        }
        // loc: 1 box per thread
        int box = t;
        float area = (float)((y1v[box] - y0v[box]) * (x1v[box] - x0v[box]));
        const float eps = 1e-6f;
        float loc = g_box_in[box] / (area + eps)
                  + g_box_out[box] / ((float)PLANE - area + eps);
        g_box_in[box] = 0.0f;                          // reset for replay
        g_box_out[box] = 0.0f;

#pragma unroll
        for (int off = 16; off > 0; off >>= 1) {
            cls += __shfl_xor_sync(0xFFFFFFFFu, cls, off);
            loc += __shfl_xor_sync(0xFFFFFFFFu, loc, off);
        }
        int wid = t >> 5;
        if (lid == 0) { sCls[wid] = cls; sLoc[wid] = loc; }
        __syncthreads();
        if (t == 0) {
            float tc = 0.0f, tl = 0.0f;
#pragma unroll
            for (int w = 0; w < 8; w++) { tc += sCls[w]; tl += sLoc[w]; }
            out[0] = ALPHA * (tc / (float)N_PLANES) + BETA * (tl / (float)N_BOXES);
            g_done_count = 0u;                         // reset for replay
        }
        return;
    }

    if (blockIdx.x < N_BOXES) {
        // ================= loc block: one box =================
        int box = blockIdx.x;
        int b = box_b[box];
        int c = box_c[box];
        int y0 = y0v[box], y1 = y1v[box], x0 = x0v[box], x1 = x1v[box];

        const float4* p = reinterpret_cast<const float4*>(
            cams + ((size_t)b * K_DIM + c) * PLANE);

        float inside = 0.0f, outside = 0.0f;
#pragma unroll
        for (int i = 0; i < 4; i++) {
            int u = i * 256 + t;        // float4 index within plane [0,1024)
            float4 v = p[u];
            int row = u >> 4;           // 16 float4 per row (W=64)
            int col0 = (u & 15) << 2;
            float vals[4] = {v.x, v.y, v.z, v.w};
            bool rin = (row >= y0) && (row < y1);
#pragma unroll
            for (int j = 0; j < 4; j++) {
                int col = col0 + j;
                float e = __expf(-vals[j]);
                float s = __fdividef(1.0f, 1.0f + e);
                bool in = rin && (col >= x0) && (col < x1);
                float d = s - 1.0f;
                if (in) inside += d * d;
                else    outside += s * s;
            }
        }
#pragma unroll
        for (int off = 16; off > 0; off >>= 1) {
            inside  += __shfl_xor_sync(0xFFFFFFFFu, inside, off);
            outside += __shfl_xor_sync(0xFFFFFFFFu, outside, off);
        }
        if (lid == 0) {
            red_add_f32(&g_box_in[box], inside);       // fire-and-forget
            red_add_f32(&g_box_out[box], outside);
        }
    } else {
        // ================= cls block: one (b,k) plane =================
        int plane = blockIdx.x - N_BOXES;
        const float4* p = reinterpret_cast<const float4*>(cams + (size_t)plane * PLANE);

        float m = -INFINITY;
#pragma unroll
        for (int i = 0; i < 4; i++) {
            float4 v = p[i * 256 + t];
            m = fmaxf(m, fmaxf(fmaxf(v.x, v.y), fmaxf(v.z, v.w)));
        }
        unsigned int em = __reduce_max_sync(0xFFFFFFFFu, enc_f(m));
        if (lid == 0)
            red_max_u32(&g_plane_max[plane], em);      // fire-and-forget
    }

    // Block completion: bar orders all warps' REDs before t0's release-red.
    __syncthreads();
    if (t == 0)
        red_add_release_gpu(&g_done_count, 1u);
}

extern "C" void kernel_launch(void* const* d_in, const int* in_sizes, int n_in,
                              void* d_out, int out_size) {
    const float* cams        = (const float*)d_in[0];
    const float* concepts_gt = (const float*)d_in[1];
    const int*   box_b       = (const int*)d_in[2];
    const int*   box_c       = (const int*)d_in[3];
    const int*   y0          = (const int*)d_in[4];
    const int*   y1          = (const int*)d_in[5];
    const int*   x0          = (const int*)d_in[6];
    const int*   x1          = (const int*)d_in[7];
    float* out = (float*)d_out;

    fused_loss_kernel<<<N_BLOCKS, 256>>>(cams, concepts_gt, box_b, box_c,
                                         y0, y1, x0, x1, out);
}

// round 14
// speedup vs baseline: 1.5377x; 1.5377x over previous
#include <cuda_runtime.h>
#include <math.h>

#define B_DIM 64
#define K_DIM 128
#define H_DIM 64
#define W_DIM 64
#define PLANE (H_DIM * W_DIM)          // 4096 floats
#define N_PLANES (B_DIM * K_DIM)       // 8192
#define N_BOXES 256
#define N_BLOCKS (N_PLANES + N_BOXES)  // 8448
#define ALPHA 1.0f
#define BETA 0.5f
#define NPART 32
#define PART_STRIDE 32                 // 128B between accumulator slots

// Zero-initialized device globals; finalize kernel resets them each run.
__device__ float g_cls_parts[NPART * PART_STRIDE];
__device__ float g_loc_parts[NPART * PART_STRIDE];

__device__ __forceinline__ float softplus_f(float x) {
    float ax = fabsf(x);
    return log1pf(expf(-ax)) + fmaxf(x, 0.0f);
}

// Kernel 1: loc blocks [0,256) then cls blocks [256,8448).
// Block epilogue = ONE fire-and-forget atomicAdd (return unused -> RED).
__global__ __launch_bounds__(256) void main_kernel(
    const float* __restrict__ cams,
    const float* __restrict__ concepts_gt,
    const int* __restrict__ box_b,
    const int* __restrict__ box_c,
    const int* __restrict__ y0v,
    const int* __restrict__ y1v,
    const int* __restrict__ x0v,
    const int* __restrict__ x1v)
{
    int t = threadIdx.x;
    int wid = t >> 5, lid = t & 31;
    __shared__ float s0[8], s1[8];

    if (blockIdx.x < N_BOXES) {
        // ---------------- loc block: one box ----------------
        int box = blockIdx.x;
        int b = box_b[box];
        int c = box_c[box];
        int y0 = y0v[box], y1 = y1v[box], x0 = x0v[box], x1 = x1v[box];

        const float4* p = reinterpret_cast<const float4*>(
            cams + ((size_t)b * K_DIM + c) * PLANE);

        float inside = 0.0f, outside = 0.0f;
#pragma unroll
        for (int i = 0; i < 4; i++) {
            int u = i * 256 + t;        // float4 index within plane [0,1024)
            float4 v = p[u];
            int row = u >> 4;           // 16 float4 per row (W=64)
            int col0 = (u & 15) << 2;
            float vals[4] = {v.x, v.y, v.z, v.w};
            bool rin = (row >= y0) && (row < y1);
#pragma unroll
            for (int j = 0; j < 4; j++) {
                int col = col0 + j;
                float e = __expf(-vals[j]);
                float s = __fdividef(1.0f, 1.0f + e);
                bool in = rin && (col >= x0) && (col < x1);
                float d = s - 1.0f;
                if (in) inside += d * d;
                else    outside += s * s;
            }
        }
#pragma unroll
        for (int off = 16; off > 0; off >>= 1) {
            inside  += __shfl_xor_sync(0xFFFFFFFFu, inside, off);
            outside += __shfl_xor_sync(0xFFFFFFFFu, outside, off);
        }
        if (lid == 0) { s0[wid] = inside; s1[wid] = outside; }
        __syncthreads();
        if (t == 0) {
            float ti = 0.0f, to = 0.0f;
#pragma unroll
            for (int w = 0; w < 8; w++) { ti += s0[w]; to += s1[w]; }
            float area = (float)((y1 - y0) * (x1 - x0));
            const float eps = 1e-6f;
            float loss = ti / (area + eps) + to / ((float)PLANE - area + eps);
            atomicAdd(&g_loc_parts[(box & (NPART - 1)) * PART_STRIDE], loss);
        }
    } else {
        // ---------------- cls block: one (b,k) plane ----------------
        int plane = blockIdx.x - N_BOXES;
        const float4* p = reinterpret_cast<const float4*>(cams + (size_t)plane * PLANE);

        float m = -INFINITY;
#pragma unroll
        for (int i = 0; i < 4; i++) {
            float4 v = p[i * 256 + t];
            m = fmaxf(m, fmaxf(fmaxf(v.x, v.y), fmaxf(v.z, v.w)));
        }
#pragma unroll
        for (int off = 16; off > 0; off >>= 1)
            m = fmaxf(m, __shfl_xor_sync(0xFFFFFFFFu, m, off));
        if (lid == 0) s0[wid] = m;
        __syncthreads();
        if (t == 0) {
            float bm = s0[0];
#pragma unroll
            for (int w = 1; w < 8; w++) bm = fmaxf(bm, s0[w]);
            float y = concepts_gt[plane];
            float bce = y * softplus_f(-bm) + (1.0f - y) * softplus_f(bm);
            atomicAdd(&g_cls_parts[(plane & (NPART - 1)) * PART_STRIDE], bce);
        }
    }
}

// Kernel 2 (PDL secondary): launch overlaps kernel 1; grid-dependency sync
// waits for kernel 1's completion (and memory visibility) before reading.
__global__ void finalize_kernel(float* __restrict__ out) {
    cudaGridDependencySynchronize();

    int lid = threadIdx.x;   // 32 threads
    float cls = g_cls_parts[lid * PART_STRIDE];
    float loc = g_loc_parts[lid * PART_STRIDE];
    g_cls_parts[lid * PART_STRIDE] = 0.0f;
    g_loc_parts[lid * PART_STRIDE] = 0.0f;
#pragma unroll
    for (int off = 16; off > 0; off >>= 1) {
        cls += __shfl_xor_sync(0xFFFFFFFFu, cls, off);
        loc += __shfl_xor_sync(0xFFFFFFFFu, loc, off);
    }
    if (lid == 0)
        out[0] = ALPHA * (cls / (float)N_PLANES) + BETA * (loc / (float)N_BOXES);
}

extern "C" void kernel_launch(void* const* d_in, const int* in_sizes, int n_in,
                              void* d_out, int out_size) {
    const float* cams        = (const float*)d_in[0];
    const float* concepts_gt = (const float*)d_in[1];
    const int*   box_b       = (const int*)d_in[2];
    const int*   box_c       = (const int*)d_in[3];
    const int*   y0          = (const int*)d_in[4];
    const int*   y1          = (const int*)d_in[5];
    const int*   x0          = (const int*)d_in[6];
    const int*   x1          = (const int*)d_in[7];
    float* out = (float*)d_out;

    main_kernel<<<N_BLOCKS, 256>>>(cams, concepts_gt, box_b, box_c, y0, y1, x0, x1);

    // PDL launch of the finalizer: overlaps launch latency with main_kernel.
    cudaLaunchConfig_t cfg = {};
    cfg.gridDim  = dim3(1, 1, 1);
    cfg.blockDim = dim3(32, 1, 1);
    cfg.dynamicSmemBytes = 0;
    cfg.stream = 0;   // legacy default stream (same as <<<>>>)
    cudaLaunchAttribute attr;
    attr.id = cudaLaunchAttributeProgrammaticStreamSerialization;
    attr.val.programmaticStreamSerializationAllowed = 1;
    cfg.attrs = &attr;
    cfg.numAttrs = 1;
    cudaLaunchKernelEx(&cfg, finalize_kernel, out);
}